// round 12
// baseline (speedup 1.0000x reference)
#include <cuda_runtime.h>
#include <cuda_bf16.h>
#include <cstdint>

// Off-diagonal Gram sum via:
//   (1/D) sum_d [ (sum_b x2[b,d])^2 - sum_b x2[b,d]^2 ],  x2 = x*x.
//
// R12: merge the two independently-best ingredients:
//   - LDG.256 (R11: best cold dur, halves request count)
//   - 32 warps/SM via grid=294 x 512 (R9/R10: only config hitting 8.704)
// Warp-internal 8-way b-split (lane = 4q + c): each thread stages 4
// unpredicated LDG.256 for rows q*4..q*4+3 of one 8-float chunk.
// s recombined across 8 lanes via shfl_xor 4/8/16; x^4 additive.

#define B_ROWS 32
#define THREADS 512
#define ROWS_PT 4                // b-rows per thread (32 / 8 octants)
#define D_CONST 150528
#define D8_CONST (D_CONST / 8)   // 18816 = 294 * 16 * 4

__device__ double g_acc = 0.0;
__device__ unsigned int g_count = 0;

typedef unsigned long long u64;

__device__ __forceinline__ void upk2(u64 v, float& lo, float& hi) {
    asm("mov.b64 {%0, %1}, %2;" : "=f"(lo), "=f"(hi) : "l"(v));
}
__device__ __forceinline__ u64 mul2(u64 a, u64 b) {
    u64 r; asm("mul.rn.f32x2 %0, %1, %2;" : "=l"(r) : "l"(a), "l"(b)); return r;
}
__device__ __forceinline__ u64 add2(u64 a, u64 b) {
    u64 r; asm("add.rn.f32x2 %0, %1, %2;" : "=l"(r) : "l"(a), "l"(b)); return r;
}
__device__ __forceinline__ u64 fma2(u64 a, u64 b, u64 c) {
    u64 r; asm("fma.rn.f32x2 %0, %1, %2, %3;" : "=l"(r) : "l"(a), "l"(b), "l"(c)); return r;
}

struct U256 { u64 a, b, c, d; };
__device__ __forceinline__ U256 ldg256(const float* p) {
    U256 r;
    asm volatile("ld.global.v4.b64 {%0, %1, %2, %3}, [%4];"
                 : "=l"(r.a), "=l"(r.b), "=l"(r.c), "=l"(r.d)
                 : "l"(p));
    return r;
}

__global__ void __launch_bounds__(THREADS, 2)
ortho_fixed_kernel(const float* __restrict__ in, float* __restrict__ out,
                   double inv_d, int nblocks) {
    const int tid  = threadIdx.x;
    const int lane = tid & 31;
    const int q    = lane >> 2;                       // b-octant 0..7
    const int c    = lane & 3;                        // chunk slot within warp
    const int wid  = tid >> 5;
    const int gw   = blockIdx.x * (THREADS / 32) + wid;   // 294*16 = 4704 warps
    const int col8 = gw * 4 + c;                      // 4704*4 = 18816 = D8 exact

    // 4 staged 256-bit loads: rows q*4 .. q*4+3, 8 consecutive floats each.
    // 32B-aligned: col8*32 B and row*D*4 B (D % 8 == 0) are multiples of 32.
    const float* p = in + (size_t)(q * ROWS_PT) * D_CONST + (size_t)col8 * 8;
    U256 v[ROWS_PT];
    #pragma unroll
    for (int j = 0; j < ROWS_PT; j++)
        v[j] = ldg256(p + (size_t)j * D_CONST);

    u64 s0 = 0ull, s1 = 0ull, s2 = 0ull, s3 = 0ull;
    u64 t0 = 0ull, t1 = 0ull, t2 = 0ull, t3 = 0ull;
    #pragma unroll
    for (int j = 0; j < ROWS_PT; j++) {
        u64 a0 = mul2(v[j].a, v[j].a);
        u64 a1 = mul2(v[j].b, v[j].b);
        u64 a2 = mul2(v[j].c, v[j].c);
        u64 a3 = mul2(v[j].d, v[j].d);
        s0 = add2(s0, a0); t0 = fma2(a0, a0, t0);
        s1 = add2(s1, a1); t1 = fma2(a1, a1, t1);
        s2 = add2(s2, a2); t2 = fma2(a2, a2, t2);
        s3 = add2(s3, a3); t3 = fma2(a3, a3, t3);
    }

    // local x^4 sum (additive across octants)
    float ta, tb, tsum = 0.f;
    upk2(t0, ta, tb); tsum += ta + tb;
    upk2(t1, ta, tb); tsum += ta + tb;
    upk2(t2, ta, tb); tsum += ta + tb;
    upk2(t3, ta, tb); tsum += ta + tb;

    // recombine s across the 8 b-octants (lanes c, c+4, ..., c+28)
    #pragma unroll
    for (int m = 4; m <= 16; m <<= 1) {
        s0 = add2(s0, __shfl_xor_sync(0xFFFFFFFFu, s0, m));
        s1 = add2(s1, __shfl_xor_sync(0xFFFFFFFFu, s1, m));
        s2 = add2(s2, __shfl_xor_sync(0xFFFFFFFFu, s2, m));
        s3 = add2(s3, __shfl_xor_sync(0xFFFFFFFFu, s3, m));
    }

    float val = -tsum;
    if (q == 0) {
        float x, y, ss = 0.f;
        upk2(s0, x, y); ss += x * x + y * y;
        upk2(s1, x, y); ss += x * x + y * y;
        upk2(s2, x, y); ss += x * x + y * y;
        upk2(s3, x, y); ss += x * x + y * y;
        val += ss;
    }

    #pragma unroll
    for (int off = 16; off > 0; off >>= 1)
        val += __shfl_xor_sync(0xFFFFFFFFu, val, off);

    __shared__ float warp_sums[THREADS / 32];
    if (lane == 0) warp_sums[wid] = val;
    __syncthreads();

    if (wid == 0) {
        float blk = (lane < THREADS / 32) ? warp_sums[lane] : 0.f;
        #pragma unroll
        for (int off = 8; off > 0; off >>= 1)
            blk += __shfl_xor_sync(0xFFFFFFFFu, blk, off);
        if (lane == 0) {
            atomicAdd(&g_acc, (double)blk);
            __threadfence();
            unsigned int ticket = atomicAdd(&g_count, 1u);
            if (ticket == (unsigned int)nblocks - 1u) {
                out[0] = (float)(g_acc * inv_d);
                g_acc = 0.0;     // reset for next graph replay
                g_count = 0u;
            }
        }
    }
}

// Generic fallback (runtime shape), identical math.
__global__ void __launch_bounds__(256, 1)
ortho_generic_kernel(const float4* __restrict__ in, float* __restrict__ out,
                     int d4, double inv_d, int nblocks) {
    int idx = blockIdx.x * 256 + threadIdx.x;
    float s0 = 0.f, s1 = 0.f, s2 = 0.f, s3 = 0.f;
    float t0 = 0.f, t1 = 0.f, t2 = 0.f, t3 = 0.f;
    if (idx < d4) {
        #pragma unroll
        for (int b = 0; b < B_ROWS; b++) {
            float4 v = in[(size_t)b * d4 + idx];
            float a0 = v.x * v.x, a1 = v.y * v.y, a2 = v.z * v.z, a3 = v.w * v.w;
            s0 += a0; t0 = fmaf(a0, a0, t0);
            s1 += a1; t1 = fmaf(a1, a1, t1);
            s2 += a2; t2 = fmaf(a2, a2, t2);
            s3 += a3; t3 = fmaf(a3, a3, t3);
        }
    }
    float val = (fmaf(s0, s0, -t0) + fmaf(s1, s1, -t1))
              + (fmaf(s2, s2, -t2) + fmaf(s3, s3, -t3));
    #pragma unroll
    for (int off = 16; off > 0; off >>= 1)
        val += __shfl_xor_sync(0xFFFFFFFFu, val, off);
    __shared__ float ws[8];
    int lane = threadIdx.x & 31, wid = threadIdx.x >> 5;
    if (lane == 0) ws[wid] = val;
    __syncthreads();
    if (wid == 0) {
        float blk = (lane < 8) ? ws[lane] : 0.f;
        #pragma unroll
        for (int off = 4; off > 0; off >>= 1)
            blk += __shfl_xor_sync(0xFFFFFFFFu, blk, off);
        if (lane == 0) {
            atomicAdd(&g_acc, (double)blk);
            __threadfence();
            unsigned int ticket = atomicAdd(&g_count, 1u);
            if (ticket == (unsigned int)nblocks - 1u) {
                out[0] = (float)(g_acc * inv_d);
                g_acc = 0.0;
                g_count = 0u;
            }
        }
    }
}

extern "C" void kernel_launch(void* const* d_in, const int* in_sizes, int n_in,
                              void* d_out, int out_size) {
    int total = in_sizes[0];
    int D = total / B_ROWS;

    if (D == D_CONST) {
        int blocks = D8_CONST / ((THREADS / 32) * 4);   // 294, exact
        ortho_fixed_kernel<<<blocks, THREADS>>>((const float*)d_in[0], (float*)d_out,
                                                1.0 / (double)D, blocks);
    } else {
        int d4 = D / 4;
        int blocks = (d4 + 255) / 256;
        ortho_generic_kernel<<<blocks, 256>>>((const float4*)d_in[0], (float*)d_out,
                                              d4, 1.0 / (double)D, blocks);
    }
}

// round 13
// speedup vs baseline: 1.0294x; 1.0294x over previous
#include <cuda_runtime.h>
#include <cuda_bf16.h>
#include <cstdint>

// Off-diagonal Gram sum via:
//   (1/D) sum_d [ (sum_b x2[b,d])^2 - sum_b x2[b,d]^2 ],  x2 = x*x.
//
// Final (R10 config, converged): 294 CTAs x 512 thr (32 warps/SM),
// warp-internal 4-way b-split (lane = 8q + c), 8 staged LDG.128/thread
// at compile-time-constant strides, packed f32x2 inner math, shfl-only
// s-recombine, single fused kernel with last-block finalize.
// 12 rounds established a ~8.7us bench floor (graph-replay overhead +
// clock-unramped hot phase); this config hit it with the best cold
// profile (ncu 8.19us, DRAM 30%, occ 36%).

#define B_ROWS 32
#define THREADS 512
#define QROWS 8
#define D4_CONST 37632          // 150528 / 4

__device__ double g_acc = 0.0;
__device__ unsigned int g_count = 0;

__device__ __forceinline__ unsigned long long pk2(float lo, float hi) {
    unsigned long long r;
    asm("mov.b64 %0, {%1, %2};" : "=l"(r) : "f"(lo), "f"(hi));
    return r;
}
__device__ __forceinline__ void upk2(unsigned long long v, float& lo, float& hi) {
    asm("mov.b64 {%0, %1}, %2;" : "=f"(lo), "=f"(hi) : "l"(v));
}
__device__ __forceinline__ unsigned long long mul2(unsigned long long a, unsigned long long b) {
    unsigned long long r;
    asm("mul.rn.f32x2 %0, %1, %2;" : "=l"(r) : "l"(a), "l"(b));
    return r;
}
__device__ __forceinline__ unsigned long long add2(unsigned long long a, unsigned long long b) {
    unsigned long long r;
    asm("add.rn.f32x2 %0, %1, %2;" : "=l"(r) : "l"(a), "l"(b));
    return r;
}
__device__ __forceinline__ unsigned long long fma2(unsigned long long a, unsigned long long b,
                                                   unsigned long long c) {
    unsigned long long r;
    asm("fma.rn.f32x2 %0, %1, %2, %3;" : "=l"(r) : "l"(a), "l"(b), "l"(c));
    return r;
}

template <int D4>
__device__ __forceinline__ void ortho_body(const float4* __restrict__ in,
                                           float* __restrict__ out,
                                           double inv_d, int nblocks) {
    const int tid  = threadIdx.x;
    const int lane = tid & 31;
    const int q    = lane >> 3;                       // b-quarter 0..3
    const int c    = lane & 7;                        // column within warp
    const int wid  = tid >> 5;
    const int gw   = blockIdx.x * (THREADS / 32) + wid;
    const int col  = gw * 8 + c;

    // 8 staged loads at compile-time-constant offsets from one base
    const float4* p = in + (size_t)(q * QROWS) * D4 + col;
    float4 v[QROWS];
    #pragma unroll
    for (int j = 0; j < QROWS; j++)
        v[j] = p[(size_t)j * D4];

    unsigned long long s01 = 0ull, s23 = 0ull, t01 = 0ull, t23 = 0ull;
    #pragma unroll
    for (int j = 0; j < QROWS; j++) {
        unsigned long long v01 = pk2(v[j].x, v[j].y);
        unsigned long long v23 = pk2(v[j].z, v[j].w);
        unsigned long long a01 = mul2(v01, v01);
        unsigned long long a23 = mul2(v23, v23);
        s01 = add2(s01, a01);
        s23 = add2(s23, a23);
        t01 = fma2(a01, a01, t01);
        t23 = fma2(a23, a23, t23);
    }

    float sx, sy, sz, sw, tx, ty, tz, tw;
    upk2(s01, sx, sy); upk2(s23, sz, sw);
    upk2(t01, tx, ty); upk2(t23, tz, tw);
    float tsum = (tx + ty) + (tz + tw);

    // recombine s across the 4 b-quarters (lanes c, c+8, c+16, c+24)
    sx += __shfl_xor_sync(0xFFFFFFFFu, sx, 8);
    sx += __shfl_xor_sync(0xFFFFFFFFu, sx, 16);
    sy += __shfl_xor_sync(0xFFFFFFFFu, sy, 8);
    sy += __shfl_xor_sync(0xFFFFFFFFu, sy, 16);
    sz += __shfl_xor_sync(0xFFFFFFFFu, sz, 8);
    sz += __shfl_xor_sync(0xFFFFFFFFu, sz, 16);
    sw += __shfl_xor_sync(0xFFFFFFFFu, sw, 8);
    sw += __shfl_xor_sync(0xFFFFFFFFu, sw, 16);

    float val = -tsum;
    if (q == 0)
        val += (sx * sx + sy * sy) + (sz * sz + sw * sw);

    #pragma unroll
    for (int off = 16; off > 0; off >>= 1)
        val += __shfl_xor_sync(0xFFFFFFFFu, val, off);

    __shared__ float warp_sums[THREADS / 32];
    if (lane == 0) warp_sums[wid] = val;
    __syncthreads();

    // warp 0 finishes: 16 partials -> lane-parallel shfl tree -> one atomic
    if (wid == 0) {
        float blk = (lane < THREADS / 32) ? warp_sums[lane] : 0.f;
        #pragma unroll
        for (int off = 8; off > 0; off >>= 1)
            blk += __shfl_xor_sync(0xFFFFFFFFu, blk, off);
        if (lane == 0) {
            atomicAdd(&g_acc, (double)blk);
            __threadfence();
            unsigned int ticket = atomicAdd(&g_count, 1u);
            if (ticket == (unsigned int)nblocks - 1u) {
                out[0] = (float)(g_acc * inv_d);
                g_acc = 0.0;     // reset for next graph replay
                g_count = 0u;
            }
        }
    }
}

__global__ void __launch_bounds__(THREADS, 2)
ortho_fixed_kernel(const float4* __restrict__ in, float* __restrict__ out,
                   double inv_d, int nblocks) {
    ortho_body<D4_CONST>(in, out, inv_d, nblocks);
}

// Generic fallback (runtime d4), identical math.
__global__ void __launch_bounds__(256, 1)
ortho_generic_kernel(const float4* __restrict__ in, float* __restrict__ out,
                     int d4, double inv_d, int nblocks) {
    int idx = blockIdx.x * 256 + threadIdx.x;
    float s0 = 0.f, s1 = 0.f, s2 = 0.f, s3 = 0.f;
    float t0 = 0.f, t1 = 0.f, t2 = 0.f, t3 = 0.f;
    if (idx < d4) {
        #pragma unroll
        for (int b = 0; b < B_ROWS; b++) {
            float4 v = in[(size_t)b * d4 + idx];
            float a0 = v.x * v.x, a1 = v.y * v.y, a2 = v.z * v.z, a3 = v.w * v.w;
            s0 += a0; t0 = fmaf(a0, a0, t0);
            s1 += a1; t1 = fmaf(a1, a1, t1);
            s2 += a2; t2 = fmaf(a2, a2, t2);
            s3 += a3; t3 = fmaf(a3, a3, t3);
        }
    }
    float val = (fmaf(s0, s0, -t0) + fmaf(s1, s1, -t1))
              + (fmaf(s2, s2, -t2) + fmaf(s3, s3, -t3));
    #pragma unroll
    for (int off = 16; off > 0; off >>= 1)
        val += __shfl_xor_sync(0xFFFFFFFFu, val, off);
    __shared__ float ws[8];
    int lane = threadIdx.x & 31, wid = threadIdx.x >> 5;
    if (lane == 0) ws[wid] = val;
    __syncthreads();
    if (wid == 0) {
        float blk = (lane < 8) ? ws[lane] : 0.f;
        #pragma unroll
        for (int off = 4; off > 0; off >>= 1)
            blk += __shfl_xor_sync(0xFFFFFFFFu, blk, off);
        if (lane == 0) {
            atomicAdd(&g_acc, (double)blk);
            __threadfence();
            unsigned int ticket = atomicAdd(&g_count, 1u);
            if (ticket == (unsigned int)nblocks - 1u) {
                out[0] = (float)(g_acc * inv_d);
                g_acc = 0.0;
                g_count = 0u;
            }
        }
    }
}

extern "C" void kernel_launch(void* const* d_in, const int* in_sizes, int n_in,
                              void* d_out, int out_size) {
    const float4* in = (const float4*)d_in[0];
    float* out = (float*)d_out;

    int total = in_sizes[0];
    int D = total / B_ROWS;
    int d4 = D / 4;

    if (d4 == D4_CONST) {
        int blocks = D4_CONST / ((THREADS / 32) * 8);   // 294, exact
        ortho_fixed_kernel<<<blocks, THREADS>>>(in, out, 1.0 / (double)D, blocks);
    } else {
        int blocks = (d4 + 255) / 256;
        ortho_generic_kernel<<<blocks, 256>>>(in, out, d4, 1.0 / (double)D, blocks);
    }
}